// round 7
// baseline (speedup 1.0000x reference)
#include <cuda_runtime.h>
#include <cuda_bf16.h>
#include <cstdint>
#include <cstddef>

#define BQ 64
#define TQ 512
#define DQ 1024
#define HQ 1024
#define ZN 4096   // 4H
#define NCTA 128  // scan CTAs; CTA j owns h cols [8j, 8j+8)

// ---------------- scratch (allocation-free __device__ globals) ----------------
__device__ float g_xz[(size_t)BQ * TQ * ZN];          // 512 MB: x @ Wi + b
// h in MMA A-fragment order, bf16 split, double-buffered by step parity:
// [buf][k16-chunk 0..63][m-tile 0..3][lane] = uint4 (a0,a1,a2,a3)
__device__ uint4 g_hfH[2][64][4][32];
__device__ uint4 g_hfL[2][64][4][32];
__device__ int   g_flag[NCTA];
__device__ int   g_done[8];                            // phase-1 t-chunk completion

// ---------------- helpers ----------------
__device__ __forceinline__ void bsplit(float v, uint16_t& h, uint16_t& l) {
    __nv_bfloat16 bh = __float2bfloat16(v);
    __nv_bfloat16 bl = __float2bfloat16(v - __bfloat162float(bh));
    h = __bfloat16_as_ushort(bh);
    l = __bfloat16_as_ushort(bl);
}
__device__ __forceinline__ void pack2(float v0, float v1, uint32_t& hi, uint32_t& lo) {
    uint16_t h0, l0, h1, l1;
    bsplit(v0, h0, l0); bsplit(v1, h1, l1);
    hi = (uint32_t)h0 | ((uint32_t)h1 << 16);
    lo = (uint32_t)l0 | ((uint32_t)l1 << 16);
}
__device__ __forceinline__ void mma16816(float c[4], uint32_t a0, uint32_t a1,
                                         uint32_t a2, uint32_t a3,
                                         uint32_t b0, uint32_t b1) {
    asm volatile(
        "mma.sync.aligned.m16n8k16.row.col.f32.bf16.bf16.f32 "
        "{%0,%1,%2,%3},{%4,%5,%6,%7},{%8,%9},{%0,%1,%2,%3};"
        : "+f"(c[0]), "+f"(c[1]), "+f"(c[2]), "+f"(c[3])
        : "r"(a0), "r"(a1), "r"(a2), "r"(a3), "r"(b0), "r"(b1));
}
__device__ __forceinline__ uint4 ldg_cg_v4(const uint4* p) {
    uint4 v;
    asm volatile("ld.global.cg.v4.b32 {%0,%1,%2,%3},[%4];"
                 : "=r"(v.x), "=r"(v.y), "=r"(v.z), "=r"(v.w) : "l"(p));
    return v;
}
__device__ __forceinline__ int ld_acq(const int* p) {
    int v;
    asm volatile("ld.global.acquire.gpu.b32 %0,[%1];" : "=r"(v) : "l"(p) : "memory");
    return v;
}
__device__ __forceinline__ void st_rel(int* p, int v) {
    asm volatile("st.global.release.gpu.b32 [%0],%1;" :: "l"(p), "r"(v) : "memory");
}
// 1-MUFU approx sigmoid (abs err ~2.4e-4): 0.5 + 0.5*tanh.approx(x/2)
__device__ __forceinline__ float sig_fast(float x) {
    float y;
    asm("tanh.approx.f32 %0,%1;" : "=f"(y) : "f"(0.5f * x));
    return fmaf(0.5f, y, 0.5f);
}
// 2-MUFU accurate tanh (~1e-6): 2/(1+e^{-2x}) - 1
__device__ __forceinline__ float tanh_acc(float x) {
    float e = __expf(-2.0f * x);
    return __fdividef(2.0f, 1.0f + e) - 1.0f;
}

// ---------------- init: h0 -> frag buffer 0, reset flags/counters ----------------
__global__ __launch_bounds__(256) void init_kernel(const float* __restrict__ h0) {
    int u = blockIdx.x * 256 + threadIdx.x;          // 8192 = 64*4*32
    if (u < NCTA) g_flag[u] = 0;
    if (u < 8)    g_done[u] = 0;
    int lane = u & 31, mt = (u >> 5) & 3, kk = u >> 7;
    int grp = lane >> 2, tig = lane & 3;
    int r0 = mt * 16 + grp, r1 = r0 + 8;
    int k0 = kk * 16 + 2 * tig;
    float2 v00 = *(const float2*)&h0[(size_t)r0 * HQ + k0];
    float2 v10 = *(const float2*)&h0[(size_t)r1 * HQ + k0];
    float2 v01 = *(const float2*)&h0[(size_t)r0 * HQ + k0 + 8];
    float2 v11 = *(const float2*)&h0[(size_t)r1 * HQ + k0 + 8];
    uint4 H, L;
    pack2(v00.x, v00.y, H.x, L.x);
    pack2(v10.x, v10.y, H.y, L.y);
    pack2(v01.x, v01.y, H.z, L.z);
    pack2(v11.x, v11.y, H.w, L.w);
    g_hfH[0][kk][mt][lane] = H;
    g_hfL[0][kk][mt][lane] = L;
}

// ---------------- phase 1: xz = x @ Wi + b  (M=32768,N=4096,K=1024) ----------------
// 1-D grid ordered by t-chunk: id = tc*2048 + b*32 + n. CTA tile 64x128, BK=32.
__global__ __launch_bounds__(256, 2) void gemm_split_kernel(
    const float* __restrict__ A, const float* __restrict__ Bm,
    const float* __restrict__ bias, float* __restrict__ C, int N, int K)
{
    __shared__ uint32_t AsH[64][20], AsL[64][20];
    __shared__ uint32_t BsH[16][136], BsL[16][136];

    const int tid  = threadIdx.x;
    const int lane = tid & 31, warp = tid >> 5;
    const int grp = lane >> 2, tig = lane & 3;
    const int wr = (warp >> 2) << 5;
    const int wc = (warp & 3) << 5;

    const int id  = blockIdx.x;
    const int tc  = id >> 11;            // t-chunk 0..7
    const int rem = id & 2047;
    const int bb  = rem >> 5, nn = rem & 31;
    const int mbase = (bb * 8 + tc) * 64;
    const int nbase = nn * 128;

    float acc[2][4][4];
    #pragma unroll
    for (int i = 0; i < 2; i++)
        #pragma unroll
        for (int j = 0; j < 4; j++)
            #pragma unroll
            for (int q = 0; q < 4; q++) acc[i][j][q] = 0.f;

    for (int k0 = 0; k0 < K; k0 += 32) {
        #pragma unroll
        for (int i = 0; i < 2; i++) {
            int idx = tid + i * 256;
            int r = idx >> 3, q = idx & 7;
            float4 v = *reinterpret_cast<const float4*>(&A[(size_t)(mbase + r) * K + k0 + q * 4]);
            pack2(v.x, v.y, AsH[r][q * 2],     AsL[r][q * 2]);
            pack2(v.z, v.w, AsH[r][q * 2 + 1], AsL[r][q * 2 + 1]);
        }
        #pragma unroll
        for (int i = 0; i < 2; i++) {
            int idx = tid + i * 256;
            int p = idx >> 5, ng = idx & 31;
            const float4 r0 = *reinterpret_cast<const float4*>(&Bm[(size_t)(k0 + 2 * p) * N + nbase + ng * 4]);
            const float4 r1 = *reinterpret_cast<const float4*>(&Bm[(size_t)(k0 + 2 * p + 1) * N + nbase + ng * 4]);
            pack2(r0.x, r1.x, BsH[p][ng * 4 + 0], BsL[p][ng * 4 + 0]);
            pack2(r0.y, r1.y, BsH[p][ng * 4 + 1], BsL[p][ng * 4 + 1]);
            pack2(r0.z, r1.z, BsH[p][ng * 4 + 2], BsL[p][ng * 4 + 2]);
            pack2(r0.w, r1.w, BsH[p][ng * 4 + 3], BsL[p][ng * 4 + 3]);
        }
        __syncthreads();

        #pragma unroll
        for (int kk = 0; kk < 2; kk++) {
            uint32_t aH[2][4], aL[2][4], bH[4][2], bL[4][2];
            #pragma unroll
            for (int mi = 0; mi < 2; mi++) {
                int r0 = wr + mi * 16 + grp, r1 = r0 + 8;
                int pq = kk * 8 + tig;
                aH[mi][0] = AsH[r0][pq];     aL[mi][0] = AsL[r0][pq];
                aH[mi][1] = AsH[r1][pq];     aL[mi][1] = AsL[r1][pq];
                aH[mi][2] = AsH[r0][pq + 4]; aL[mi][2] = AsL[r0][pq + 4];
                aH[mi][3] = AsH[r1][pq + 4]; aL[mi][3] = AsL[r1][pq + 4];
            }
            #pragma unroll
            for (int ni = 0; ni < 4; ni++) {
                int cc = wc + ni * 8 + grp;
                int p0 = kk * 8 + tig;
                bH[ni][0] = BsH[p0][cc];     bL[ni][0] = BsL[p0][cc];
                bH[ni][1] = BsH[p0 + 4][cc]; bL[ni][1] = BsL[p0 + 4][cc];
            }
            #pragma unroll
            for (int mi = 0; mi < 2; mi++)
                #pragma unroll
                for (int ni = 0; ni < 4; ni++) {
                    float* c = acc[mi][ni];
                    mma16816(c, aH[mi][0], aH[mi][1], aH[mi][2], aH[mi][3], bH[ni][0], bH[ni][1]);
                    mma16816(c, aH[mi][0], aH[mi][1], aH[mi][2], aH[mi][3], bL[ni][0], bL[ni][1]);
                    mma16816(c, aL[mi][0], aL[mi][1], aL[mi][2], aL[mi][3], bH[ni][0], bH[ni][1]);
                }
        }
        __syncthreads();
    }

    #pragma unroll
    for (int mi = 0; mi < 2; mi++) {
        int r0 = mbase + wr + mi * 16 + grp;
        #pragma unroll
        for (int ni = 0; ni < 4; ni++) {
            int c0 = nbase + wc + ni * 8 + tig * 2;
            float2 bv = *(const float2*)&bias[c0];
            __stcs((float2*)&C[(size_t)r0 * N + c0],
                   make_float2(acc[mi][ni][0] + bv.x, acc[mi][ni][1] + bv.y));
            __stcs((float2*)&C[(size_t)(r0 + 8) * N + c0],
                   make_float2(acc[mi][ni][2] + bv.x, acc[mi][ni][3] + bv.y));
        }
    }
    __threadfence();
    __syncthreads();
    if (tid == 0) atomicAdd(&g_done[tc], 1);
}

// ---------------- persistent scan kernel ----------------
// 128 CTAs x 256 thr. Warp (mt = wid&3, kh = wid>>2): m-tile mt, K-half kh,
// all 4 gate n-tiles. Warp waits only on its K-half's 64 producer flags.
__global__ __launch_bounds__(256, 2) void scan_kernel(
    const float* __restrict__ Wh, const float* __restrict__ c0,
    float* __restrict__ out)
{
    extern __shared__ char smem[];
    uint4* sWh = reinterpret_cast<uint4*>(smem);            // [64][4][32] uint4 = 128KB
    float* zsf = reinterpret_cast<float*>(smem + 131072);   // [2][4][64][8] = 16KB partials
    float* hs  = zsf + 4096;                                // [64][8]
    float* cs  = hs + 512;                                  // [64][8]

    const int j = blockIdx.x, tid = threadIdx.x;
    const int lane = tid & 31, warp = tid >> 5;
    const int grp = lane >> 2, tig = lane & 3;
    const int mt = warp & 3, kh = warp >> 2;
    const int kb = kh * 32;
    const int f0 = 64 * kh + lane, f1 = f0 + 32;   // this warp's producer flags

    // ---- one-time: Wh slice -> SMEM B-fragments ----
    for (int it = 0; it < 32; it++) {
        int slot = tid + it * 256;                   // 8192 slots
        int sl = slot & 31, nt = (slot >> 5) & 3, kk = slot >> 7;
        int sg = sl >> 2, st_ = sl & 3;
        int col = nt * 1024 + j * 8 + sg;
        int k0 = kk * 16 + 2 * st_;
        float w0 = Wh[(size_t)k0 * ZN + col];
        float w1 = Wh[(size_t)(k0 + 1) * ZN + col];
        float w8 = Wh[(size_t)(k0 + 8) * ZN + col];
        float w9 = Wh[(size_t)(k0 + 9) * ZN + col];
        uint4 v;
        pack2(w0, w1, v.x, v.z);
        pack2(w8, w9, v.y, v.w);
        sWh[(kk * 4 + nt) * 32 + sl] = v;
    }
    #pragma unroll
    for (int e = 0; e < 2; e++) {
        int v = tid + e * 256;
        int row = v >> 3, col = v & 7;
        cs[v] = c0[(size_t)row * HQ + j * 8 + col];
    }
    __syncthreads();

    const size_t OFF_C = (size_t)BQ * TQ * HQ;
    const size_t OFF_H = OFF_C + (size_t)BQ * HQ;

    for (int s = 0; s < TQ; s++) {
        const int buf = s & 1, nbuf = buf ^ 1;
        // gate on phase-1 t-chunk availability
        if ((s & 63) == 0) {
            if (tid == 0) {
                while (ld_acq(&g_done[s >> 6]) < 2048) __nanosleep(128);
            }
            __syncthreads();
        }

        // prefetch xz (independent of h) BEFORE the flag wait
        float xzv[2][4];
        #pragma unroll
        for (int e = 0; e < 2; e++) {
            int v = tid + e * 256;
            int row = v >> 3, col = v & 7;
            const float* xp = &g_xz[((size_t)row * TQ + s) * ZN + j * 8 + col];
            xzv[e][0] = __ldcs(xp);
            xzv[e][1] = __ldcs(xp + 1024);
            xzv[e][2] = __ldcs(xp + 2048);
            xzv[e][3] = __ldcs(xp + 3072);
        }

        // per-warp wait: only this warp's K-half producers (no block barrier)
        if (s > 0) {
            while (ld_acq(&g_flag[f0]) < s) __nanosleep(16);
            while (ld_acq(&g_flag[f1]) < s) __nanosleep(16);
            __syncwarp();
        }

        float acc[4][4];
        #pragma unroll
        for (int nt = 0; nt < 4; nt++)
            #pragma unroll
            for (int q = 0; q < 4; q++) acc[nt][q] = 0.f;

        // distance-2 prefetched A-frag loop over this warp's K-half
        uint4 A0H = ldg_cg_v4(&g_hfH[buf][kb + 0][mt][lane]);
        uint4 A0L = ldg_cg_v4(&g_hfL[buf][kb + 0][mt][lane]);
        uint4 A1H = ldg_cg_v4(&g_hfH[buf][kb + 1][mt][lane]);
        uint4 A1L = ldg_cg_v4(&g_hfL[buf][kb + 1][mt][lane]);
        #pragma unroll 4
        for (int i = 0; i < 32; i++) {
            uint4 AH = A0H, AL = A0L;
            A0H = A1H; A0L = A1L;
            if (i + 2 < 32) {
                A1H = ldg_cg_v4(&g_hfH[buf][kb + i + 2][mt][lane]);
                A1L = ldg_cg_v4(&g_hfL[buf][kb + i + 2][mt][lane]);
            }
            const int kk = kb + i;
            #pragma unroll
            for (int nt = 0; nt < 4; nt++) {
                uint4 Bv = sWh[(kk * 4 + nt) * 32 + lane];
                mma16816(acc[nt], AH.x, AH.y, AH.z, AH.w, Bv.x, Bv.y);
                mma16816(acc[nt], AH.x, AH.y, AH.z, AH.w, Bv.z, Bv.w);
                mma16816(acc[nt], AL.x, AL.y, AL.z, AL.w, Bv.x, Bv.y);
            }
        }

        // stage K-half partials
        {
            int r0 = mt * 16 + grp, r1 = r0 + 8, cc = 2 * tig;
            #pragma unroll
            for (int nt = 0; nt < 4; nt++) {
                float* zb = &zsf[((kh * 4 + nt) * 64) * 8];
                *(float2*)&zb[r0 * 8 + cc] = make_float2(acc[nt][0], acc[nt][1]);
                *(float2*)&zb[r1 * 8 + cc] = make_float2(acc[nt][2], acc[nt][3]);
            }
        }
        __syncthreads();

        // gates + state update (reduce the two K-half partials)
        #pragma unroll
        for (int e = 0; e < 2; e++) {
            int v = tid + e * 256;
            int row = v >> 3, col = v & 7;
            int o = row * 8 + col;
            float zi = zsf[(0 * 64) * 8 + o] + zsf[(4 * 64) * 8 + o] + xzv[e][0];
            float zf = zsf[(1 * 64) * 8 + o] + zsf[(5 * 64) * 8 + o] + xzv[e][1];
            float zg = zsf[(2 * 64) * 8 + o] + zsf[(6 * 64) * 8 + o] + xzv[e][2];
            float zo = zsf[(3 * 64) * 8 + o] + zsf[(7 * 64) * 8 + o] + xzv[e][3];
            float c  = cs[v];
            float nc = sig_fast(zf) * c + sig_fast(zi) * tanh_acc(zg);
            float nh = sig_fast(zo) * tanh_acc(nc);
            cs[v] = nc;
            hs[v] = nh;
            __stcs(&out[((size_t)row * TQ + s) * HQ + j * 8 + col], nh);
            if (s == TQ - 1) {
                __stcs(&out[OFF_C + (size_t)row * HQ + j * 8 + col], nc);
                __stcs(&out[OFF_H + (size_t)row * HQ + j * 8 + col], nh);
            }
        }
        __syncthreads();

        // publish new h as A-fragments into buffer nbuf
        if (tid < 128) {
            int mt2 = tid >> 5, ln = tid & 31;
            int g2 = ln >> 2, t2 = ln & 3;
            int r0 = mt2 * 16 + g2, r1 = r0 + 8, cc = 2 * t2;
            uint2 H, L;
            pack2(hs[r0 * 8 + cc], hs[r0 * 8 + cc + 1], H.x, L.x);
            pack2(hs[r1 * 8 + cc], hs[r1 * 8 + cc + 1], H.y, L.y);
            uint2* dH = reinterpret_cast<uint2*>(&g_hfH[nbuf][j >> 1][mt2][ln]);
            uint2* dL = reinterpret_cast<uint2*>(&g_hfL[nbuf][j >> 1][mt2][ln]);
            dH[j & 1] = H;
            dL[j & 1] = L;
        }
        // release pattern: barrier (intra-CTA happens-before) + release store of flag
        __syncthreads();
        if (tid == 0) st_rel(&g_flag[j], s + 1);
    }
}

// ---------------- launch: forked capture, phase1 overlaps the scan ----------------
extern "C" void kernel_launch(void* const* d_in, const int* in_sizes, int n_in,
                              void* d_out, int out_size)
{
    (void)in_sizes; (void)n_in; (void)out_size;
    const float* x  = (const float*)d_in[0];
    const float* h0 = (const float*)d_in[1];
    const float* c0 = (const float*)d_in[2];
    const float* Wi = (const float*)d_in[3];
    const float* Wh = (const float*)d_in[4];
    const float* b  = (const float*)d_in[5];
    float* out = (float*)d_out;

    float* xz_p = nullptr;
    cudaGetSymbolAddress((void**)&xz_p, g_xz);

    const int SCAN_SMEM = 131072 + 16384 + 4096;   // 151552

    static cudaStream_t s2 = nullptr;
    static cudaEvent_t evA = nullptr, evB = nullptr;
    static bool inited = false;
    if (!inited) {
        cudaStreamCreateWithFlags(&s2, cudaStreamNonBlocking);
        cudaEventCreateWithFlags(&evA, cudaEventDisableTiming);
        cudaEventCreateWithFlags(&evB, cudaEventDisableTiming);
        cudaFuncSetAttribute(scan_kernel, cudaFuncAttributeMaxDynamicSharedMemorySize, SCAN_SMEM);
        inited = true;
    }

    init_kernel<<<32, 256>>>(h0);

    // fork: phase-1 GEMM on s2, ordered after init
    cudaEventRecord(evA, 0);
    cudaStreamWaitEvent(s2, evA, 0);
    gemm_split_kernel<<<16384, 256, 0, s2>>>(x, Wi, b, xz_p, ZN, DQ);
    cudaEventRecord(evB, s2);

    // scan runs concurrently on the main stream; chunk-gated on g_done
    scan_kernel<<<NCTA, 256, SCAN_SMEM>>>(Wh, c0, out);

    // join
    cudaStreamWaitEvent(0, evB, 0);
}

// round 8
// speedup vs baseline: 1.2814x; 1.2814x over previous
#include <cuda_runtime.h>
#include <cuda_bf16.h>
#include <cstdint>
#include <cstddef>

#define BQ 64
#define TQ 512
#define DQ 1024
#define HQ 1024
#define ZN 4096   // 4H
#define NCTA 128  // scan CTAs; CTA j owns h cols [8j, 8j+8)

// ---------------- scratch (allocation-free __device__ globals) ----------------
__device__ float g_xz[(size_t)BQ * TQ * ZN];          // 512 MB: x @ Wi + b
// h in MMA A-fragment order, bf16 split, double-buffered by step parity:
// [buf][k16-chunk 0..63][m-tile 0..3][lane] = uint4 (a0,a1,a2,a3)
__device__ uint4 g_hfH[2][64][4][32];
__device__ uint4 g_hfL[2][64][4][32];
__device__ int   g_flag[NCTA];
__device__ int   g_done[8];                            // phase-1 t-chunk completion

// ---------------- helpers ----------------
__device__ __forceinline__ void bsplit(float v, uint16_t& h, uint16_t& l) {
    __nv_bfloat16 bh = __float2bfloat16(v);
    __nv_bfloat16 bl = __float2bfloat16(v - __bfloat162float(bh));
    h = __bfloat16_as_ushort(bh);
    l = __bfloat16_as_ushort(bl);
}
__device__ __forceinline__ void pack2(float v0, float v1, uint32_t& hi, uint32_t& lo) {
    uint16_t h0, l0, h1, l1;
    bsplit(v0, h0, l0); bsplit(v1, h1, l1);
    hi = (uint32_t)h0 | ((uint32_t)h1 << 16);
    lo = (uint32_t)l0 | ((uint32_t)l1 << 16);
}
__device__ __forceinline__ void mma16816(float c[4], uint32_t a0, uint32_t a1,
                                         uint32_t a2, uint32_t a3,
                                         uint32_t b0, uint32_t b1) {
    asm volatile(
        "mma.sync.aligned.m16n8k16.row.col.f32.bf16.bf16.f32 "
        "{%0,%1,%2,%3},{%4,%5,%6,%7},{%8,%9},{%0,%1,%2,%3};"
        : "+f"(c[0]), "+f"(c[1]), "+f"(c[2]), "+f"(c[3])
        : "r"(a0), "r"(a1), "r"(a2), "r"(a3), "r"(b0), "r"(b1));
}
__device__ __forceinline__ uint4 ldg_cg_v4(const uint4* p) {
    uint4 v;
    asm volatile("ld.global.cg.v4.b32 {%0,%1,%2,%3},[%4];"
                 : "=r"(v.x), "=r"(v.y), "=r"(v.z), "=r"(v.w) : "l"(p));
    return v;
}
__device__ __forceinline__ int ld_acq(const int* p) {
    int v;
    asm volatile("ld.global.acquire.gpu.b32 %0,[%1];" : "=r"(v) : "l"(p) : "memory");
    return v;
}
// 1-MUFU approx sigmoid (abs err ~2.4e-4): 0.5 + 0.5*tanh.approx(x/2)
__device__ __forceinline__ float sig_fast(float x) {
    float y;
    asm("tanh.approx.f32 %0,%1;" : "=f"(y) : "f"(0.5f * x));
    return fmaf(0.5f, y, 0.5f);
}
// 2-MUFU accurate tanh (~1e-6): 2/(1+e^{-2x}) - 1
__device__ __forceinline__ float tanh_acc(float x) {
    float e = __expf(-2.0f * x);
    return __fdividef(2.0f, 1.0f + e) - 1.0f;
}

// ---------------- init: h0 -> frag buffer 0, reset flags/counters ----------------
__global__ __launch_bounds__(256) void init_kernel(const float* __restrict__ h0) {
    int u = blockIdx.x * 256 + threadIdx.x;          // 8192 = 64*4*32
    if (u < NCTA) g_flag[u] = 0;
    if (u < 8)    g_done[u] = 0;
    int lane = u & 31, mt = (u >> 5) & 3, kk = u >> 7;
    int grp = lane >> 2, tig = lane & 3;
    int r0 = mt * 16 + grp, r1 = r0 + 8;
    int k0 = kk * 16 + 2 * tig;
    float2 v00 = *(const float2*)&h0[(size_t)r0 * HQ + k0];
    float2 v10 = *(const float2*)&h0[(size_t)r1 * HQ + k0];
    float2 v01 = *(const float2*)&h0[(size_t)r0 * HQ + k0 + 8];
    float2 v11 = *(const float2*)&h0[(size_t)r1 * HQ + k0 + 8];
    uint4 H, L;
    pack2(v00.x, v00.y, H.x, L.x);
    pack2(v10.x, v10.y, H.y, L.y);
    pack2(v01.x, v01.y, H.z, L.z);
    pack2(v11.x, v11.y, H.w, L.w);
    g_hfH[0][kk][mt][lane] = H;
    g_hfL[0][kk][mt][lane] = L;
}

// ---------------- phase 1: xz = x @ Wi + b  (M=32768,N=4096,K=1024) ----------------
// 1-D grid ordered by t-chunk: id = tc*2048 + b*32 + n. CTA tile 64x128, BK=32.
__global__ __launch_bounds__(256, 2) void gemm_split_kernel(
    const float* __restrict__ A, const float* __restrict__ Bm,
    const float* __restrict__ bias, float* __restrict__ C, int N, int K)
{
    __shared__ uint32_t AsH[64][20], AsL[64][20];
    __shared__ uint32_t BsH[16][136], BsL[16][136];

    const int tid  = threadIdx.x;
    const int lane = tid & 31, warp = tid >> 5;
    const int grp = lane >> 2, tig = lane & 3;
    const int wr = (warp >> 2) << 5;
    const int wc = (warp & 3) << 5;

    const int id  = blockIdx.x;
    const int tc  = id >> 11;            // t-chunk 0..7
    const int rem = id & 2047;
    const int bb  = rem >> 5, nn = rem & 31;
    const int mbase = (bb * 8 + tc) * 64;
    const int nbase = nn * 128;

    float acc[2][4][4];
    #pragma unroll
    for (int i = 0; i < 2; i++)
        #pragma unroll
        for (int j = 0; j < 4; j++)
            #pragma unroll
            for (int q = 0; q < 4; q++) acc[i][j][q] = 0.f;

    for (int k0 = 0; k0 < K; k0 += 32) {
        #pragma unroll
        for (int i = 0; i < 2; i++) {
            int idx = tid + i * 256;
            int r = idx >> 3, q = idx & 7;
            float4 v = *reinterpret_cast<const float4*>(&A[(size_t)(mbase + r) * K + k0 + q * 4]);
            pack2(v.x, v.y, AsH[r][q * 2],     AsL[r][q * 2]);
            pack2(v.z, v.w, AsH[r][q * 2 + 1], AsL[r][q * 2 + 1]);
        }
        #pragma unroll
        for (int i = 0; i < 2; i++) {
            int idx = tid + i * 256;
            int p = idx >> 5, ng = idx & 31;
            const float4 r0 = *reinterpret_cast<const float4*>(&Bm[(size_t)(k0 + 2 * p) * N + nbase + ng * 4]);
            const float4 r1 = *reinterpret_cast<const float4*>(&Bm[(size_t)(k0 + 2 * p + 1) * N + nbase + ng * 4]);
            pack2(r0.x, r1.x, BsH[p][ng * 4 + 0], BsL[p][ng * 4 + 0]);
            pack2(r0.y, r1.y, BsH[p][ng * 4 + 1], BsL[p][ng * 4 + 1]);
            pack2(r0.z, r1.z, BsH[p][ng * 4 + 2], BsL[p][ng * 4 + 2]);
            pack2(r0.w, r1.w, BsH[p][ng * 4 + 3], BsL[p][ng * 4 + 3]);
        }
        __syncthreads();

        #pragma unroll
        for (int kk = 0; kk < 2; kk++) {
            uint32_t aH[2][4], aL[2][4], bH[4][2], bL[4][2];
            #pragma unroll
            for (int mi = 0; mi < 2; mi++) {
                int r0 = wr + mi * 16 + grp, r1 = r0 + 8;
                int pq = kk * 8 + tig;
                aH[mi][0] = AsH[r0][pq];     aL[mi][0] = AsL[r0][pq];
                aH[mi][1] = AsH[r1][pq];     aL[mi][1] = AsL[r1][pq];
                aH[mi][2] = AsH[r0][pq + 4]; aL[mi][2] = AsL[r0][pq + 4];
                aH[mi][3] = AsH[r1][pq + 4]; aL[mi][3] = AsL[r1][pq + 4];
            }
            #pragma unroll
            for (int ni = 0; ni < 4; ni++) {
                int cc = wc + ni * 8 + grp;
                int p0 = kk * 8 + tig;
                bH[ni][0] = BsH[p0][cc];     bL[ni][0] = BsL[p0][cc];
                bH[ni][1] = BsH[p0 + 4][cc]; bL[ni][1] = BsL[p0 + 4][cc];
            }
            #pragma unroll
            for (int mi = 0; mi < 2; mi++)
                #pragma unroll
                for (int ni = 0; ni < 4; ni++) {
                    float* c = acc[mi][ni];
                    mma16816(c, aH[mi][0], aH[mi][1], aH[mi][2], aH[mi][3], bH[ni][0], bH[ni][1]);
                    mma16816(c, aH[mi][0], aH[mi][1], aH[mi][2], aH[mi][3], bL[ni][0], bL[ni][1]);
                    mma16816(c, aL[mi][0], aL[mi][1], aL[mi][2], aL[mi][3], bH[ni][0], bH[ni][1]);
                }
        }
        __syncthreads();
    }

    #pragma unroll
    for (int mi = 0; mi < 2; mi++) {
        int r0 = mbase + wr + mi * 16 + grp;
        #pragma unroll
        for (int ni = 0; ni < 4; ni++) {
            int c0 = nbase + wc + ni * 8 + tig * 2;
            float2 bv = *(const float2*)&bias[c0];
            __stcs((float2*)&C[(size_t)r0 * N + c0],
                   make_float2(acc[mi][ni][0] + bv.x, acc[mi][ni][1] + bv.y));
            __stcs((float2*)&C[(size_t)(r0 + 8) * N + c0],
                   make_float2(acc[mi][ni][2] + bv.x, acc[mi][ni][3] + bv.y));
        }
    }
    __threadfence();
    __syncthreads();
    if (tid == 0) atomicAdd(&g_done[tc], 1);
}

// ---------------- persistent scan kernel ----------------
// 128 CTAs x 512 thr (16 warps). Warp (mt = wid&3, kq = wid>>2): m-tile mt,
// K-quarter kq, all 4 gate n-tiles. 4 warps/SMSP keep the tensor pipe fed.
__global__ __launch_bounds__(512, 1) void scan_kernel(
    const float* __restrict__ Wh, const float* __restrict__ c0,
    float* __restrict__ out)
{
    extern __shared__ char smem[];
    uint4* sWh = reinterpret_cast<uint4*>(smem);            // [64][4][32] uint4 = 128KB
    float* zsf = reinterpret_cast<float*>(smem + 131072);   // [4][4][64][8] = 32KB partials
    float* hs  = zsf + 8192;                                // [64][8]
    float* cs  = hs + 512;                                  // [64][8]

    const int j = blockIdx.x, tid = threadIdx.x;
    const int lane = tid & 31, warp = tid >> 5;
    const int grp = lane >> 2, tig = lane & 3;
    const int mt = warp & 3, kq = warp >> 2;     // m-tile, K-quarter
    const int kb = kq * 16;

    // ---- one-time: Wh slice -> SMEM B-fragments ----
    for (int it = 0; it < 16; it++) {
        int slot = tid + it * 512;                   // 8192 slots
        int sl = slot & 31, nt = (slot >> 5) & 3, kk = slot >> 7;
        int sg = sl >> 2, st_ = sl & 3;
        int col = nt * 1024 + j * 8 + sg;
        int k0 = kk * 16 + 2 * st_;
        float w0 = Wh[(size_t)k0 * ZN + col];
        float w1 = Wh[(size_t)(k0 + 1) * ZN + col];
        float w8 = Wh[(size_t)(k0 + 8) * ZN + col];
        float w9 = Wh[(size_t)(k0 + 9) * ZN + col];
        uint4 v;
        pack2(w0, w1, v.x, v.z);
        pack2(w8, w9, v.y, v.w);
        sWh[(kk * 4 + nt) * 32 + sl] = v;
    }
    {
        int row = tid >> 3, col = tid & 7;
        cs[tid] = c0[(size_t)row * HQ + j * 8 + col];
    }
    __syncthreads();

    const size_t OFF_C = (size_t)BQ * TQ * HQ;
    const size_t OFF_H = OFF_C + (size_t)BQ * HQ;

    for (int s = 0; s < TQ; s++) {
        const int buf = s & 1, nbuf = buf ^ 1;
        // gate on phase-1 t-chunk availability
        if ((s & 63) == 0) {
            if (tid == 0) {
                while (ld_acq(&g_done[s >> 6]) < 2048) __nanosleep(128);
            }
            __syncthreads();
        }
        // gate on all CTAs having published h(s)
        if (s > 0) {
            if (tid < NCTA) {
                while (ld_acq(&g_flag[tid]) < s) __nanosleep(32);
            }
            __syncthreads();
        }

        // prefetch xz (DRAM, read-once streaming); consumed after the MMA loop
        float xzv[4];
        {
            int row = tid >> 3, col = tid & 7;
            const float* xp = &g_xz[((size_t)row * TQ + s) * ZN + j * 8 + col];
            xzv[0] = __ldcs(xp);
            xzv[1] = __ldcs(xp + 1024);
            xzv[2] = __ldcs(xp + 2048);
            xzv[3] = __ldcs(xp + 3072);
        }

        float acc[4][4];
        #pragma unroll
        for (int nt = 0; nt < 4; nt++)
            #pragma unroll
            for (int q = 0; q < 4; q++) acc[nt][q] = 0.f;

        // distance-2 prefetched A-frag loop over this warp's K-quarter
        uint4 A0H = ldg_cg_v4(&g_hfH[buf][kb + 0][mt][lane]);
        uint4 A0L = ldg_cg_v4(&g_hfL[buf][kb + 0][mt][lane]);
        uint4 A1H = ldg_cg_v4(&g_hfH[buf][kb + 1][mt][lane]);
        uint4 A1L = ldg_cg_v4(&g_hfL[buf][kb + 1][mt][lane]);
        #pragma unroll 4
        for (int i = 0; i < 16; i++) {
            uint4 AH = A0H, AL = A0L;
            A0H = A1H; A0L = A1L;
            if (i + 2 < 16) {
                A1H = ldg_cg_v4(&g_hfH[buf][kb + i + 2][mt][lane]);
                A1L = ldg_cg_v4(&g_hfL[buf][kb + i + 2][mt][lane]);
            }
            const int kk = kb + i;
            #pragma unroll
            for (int nt = 0; nt < 4; nt++) {
                uint4 Bv = sWh[(kk * 4 + nt) * 32 + lane];
                mma16816(acc[nt], AH.x, AH.y, AH.z, AH.w, Bv.x, Bv.y);
                mma16816(acc[nt], AH.x, AH.y, AH.z, AH.w, Bv.z, Bv.w);
                mma16816(acc[nt], AL.x, AL.y, AL.z, AL.w, Bv.x, Bv.y);
            }
        }

        // stage K-quarter partials
        {
            int r0 = mt * 16 + grp, r1 = r0 + 8, cc = 2 * tig;
            #pragma unroll
            for (int nt = 0; nt < 4; nt++) {
                float* zb = &zsf[(kq * 4 + nt) * 512];
                *(float2*)&zb[r0 * 8 + cc] = make_float2(acc[nt][0], acc[nt][1]);
                *(float2*)&zb[r1 * 8 + cc] = make_float2(acc[nt][2], acc[nt][3]);
            }
        }
        __syncthreads();

        // gates + state update (reduce the four K-quarter partials); 1 elem/thread
        {
            int row = tid >> 3, col = tid & 7;
            int o = tid;
            float zi = (zsf[0 * 512 + o] + zsf[4 * 512 + o]) + (zsf[8 * 512 + o]  + zsf[12 * 512 + o]) + xzv[0];
            float zf = (zsf[1 * 512 + o] + zsf[5 * 512 + o]) + (zsf[9 * 512 + o]  + zsf[13 * 512 + o]) + xzv[1];
            float zg = (zsf[2 * 512 + o] + zsf[6 * 512 + o]) + (zsf[10 * 512 + o] + zsf[14 * 512 + o]) + xzv[2];
            float zo = (zsf[3 * 512 + o] + zsf[7 * 512 + o]) + (zsf[11 * 512 + o] + zsf[15 * 512 + o]) + xzv[3];
            float c  = cs[o];
            float nc = sig_fast(zf) * c + sig_fast(zi) * tanh_acc(zg);
            float nh = sig_fast(zo) * tanh_acc(nc);
            cs[o] = nc;
            hs[o] = nh;
            __stcs(&out[((size_t)row * TQ + s) * HQ + j * 8 + col], nh);
            if (s == TQ - 1) {
                __stcs(&out[OFF_C + (size_t)row * HQ + j * 8 + col], nc);
                __stcs(&out[OFF_H + (size_t)row * HQ + j * 8 + col], nh);
            }
        }
        __syncthreads();

        // publish new h as A-fragments into buffer nbuf
        if (tid < 128) {
            int mt2 = tid >> 5, ln = tid & 31;
            int g2 = ln >> 2, t2 = ln & 3;
            int r0 = mt2 * 16 + g2, r1 = r0 + 8, cc = 2 * t2;
            uint2 H, L;
            pack2(hs[r0 * 8 + cc], hs[r0 * 8 + cc + 1], H.x, L.x);
            pack2(hs[r1 * 8 + cc], hs[r1 * 8 + cc + 1], H.y, L.y);
            uint2* dH = reinterpret_cast<uint2*>(&g_hfH[nbuf][j >> 1][mt2][ln]);
            uint2* dL = reinterpret_cast<uint2*>(&g_hfL[nbuf][j >> 1][mt2][ln]);
            dH[j & 1] = H;
            dL[j & 1] = L;
        }
        __threadfence();
        __syncthreads();
        if (tid == 0) atomicExch(&g_flag[j], s + 1);
    }
}

// ---------------- launch: forked capture, phase1 overlaps the scan ----------------
extern "C" void kernel_launch(void* const* d_in, const int* in_sizes, int n_in,
                              void* d_out, int out_size)
{
    (void)in_sizes; (void)n_in; (void)out_size;
    const float* x  = (const float*)d_in[0];
    const float* h0 = (const float*)d_in[1];
    const float* c0 = (const float*)d_in[2];
    const float* Wi = (const float*)d_in[3];
    const float* Wh = (const float*)d_in[4];
    const float* b  = (const float*)d_in[5];
    float* out = (float*)d_out;

    float* xz_p = nullptr;
    cudaGetSymbolAddress((void**)&xz_p, g_xz);

    const int SCAN_SMEM = 131072 + 32768 + 2048 + 2048;   // 167936

    static cudaStream_t s2 = nullptr;
    static cudaEvent_t evA = nullptr, evB = nullptr;
    static bool inited = false;
    if (!inited) {
        cudaStreamCreateWithFlags(&s2, cudaStreamNonBlocking);
        cudaEventCreateWithFlags(&evA, cudaEventDisableTiming);
        cudaEventCreateWithFlags(&evB, cudaEventDisableTiming);
        cudaFuncSetAttribute(scan_kernel, cudaFuncAttributeMaxDynamicSharedMemorySize, SCAN_SMEM);
        inited = true;
    }

    init_kernel<<<32, 256>>>(h0);

    // fork: phase-1 GEMM on s2, ordered after init
    cudaEventRecord(evA, 0);
    cudaStreamWaitEvent(s2, evA, 0);
    gemm_split_kernel<<<16384, 256, 0, s2>>>(x, Wi, b, xz_p, ZN, DQ);
    cudaEventRecord(evB, s2);

    // scan runs concurrently on the main stream; chunk-gated on g_done
    scan_kernel<<<NCTA, 512, SCAN_SMEM>>>(Wh, c0, out);

    // join
    cudaStreamWaitEvent(0, evB, 0);
}